// round 1
// baseline (speedup 1.0000x reference)
#include <cuda_runtime.h>
#include <cuda_bf16.h>
#include <cstdint>

#define BATCH   16
#define NPRED   25200
#define NC      80
#define STRIDE  85
#define TOPK    4096
#define MAXDET  1000
#define NWORDS  64            // TOPK/64
#define CONF_THRES 0.25f
#define IOU_THRES  0.45f
#define MAX_WH     7680.0f

// ---------------- scratch (no allocation allowed; __device__ globals) ----------------
__device__ unsigned            g_u[BATCH * NPRED];        // order key (score part)
__device__ float               g_s[BATCH * NPRED];        // s = valid ? conf : -1
__device__ int                 g_cls[BATCH * NPRED];      // argmax class
__device__ int                 g_selIdx[BATCH * TOPK];
__device__ float               g_selScore[BATCH * TOPK];
__device__ int                 g_selCls[BATCH * TOPK];
__device__ float               g_box[BATCH * TOPK * 4];   // xyxy (no offset)
__device__ float               g_ob[BATCH * TOPK * 4];    // offset boxes
__device__ float               g_area[BATCH * TOPK];      // area of offset box
__device__ unsigned long long  g_mask[(size_t)BATCH * TOPK * NWORDS]; // 32MB
__device__ unsigned long long  g_keep[BATCH * NWORDS];
__device__ int                 g_nvalid[BATCH];

// ---------------- kernel 1: conf / argmax / order-key, one warp per row --------------
__global__ void k_prep(const float* __restrict__ pred) {
    int gw   = (blockIdx.x * blockDim.x + threadIdx.x) >> 5;  // global warp = row
    int lane = threadIdx.x & 31;
    if (gw >= BATCH * NPRED) return;
    const float* p = pred + (size_t)gw * STRIDE;
    float obj = p[4];
    float best = -1.0f; int bi = 0;
    #pragma unroll
    for (int c = lane; c < NC; c += 32) {
        float v = __fmul_rn(obj, p[5 + c]);
        if (v > best) { best = v; bi = c; }          // strict > keeps first max
    }
    #pragma unroll
    for (int o = 16; o; o >>= 1) {
        float b2 = __shfl_xor_sync(0xFFFFFFFFu, best, o);
        int   i2 = __shfl_xor_sync(0xFFFFFFFFu, bi, o);
        if (b2 > best || (b2 == best && i2 < bi)) { best = b2; bi = i2; }
    }
    if (lane == 0) {
        float s = (best > CONF_THRES) ? best : -1.0f;
        unsigned ub = __float_as_uint(s);
        unsigned uo = (ub & 0x80000000u) ? ~ub : (ub | 0x80000000u); // ascending order map
        g_s[gw] = s; g_u[gw] = uo; g_cls[gw] = bi;
    }
}

// ---------------- kernel 2: exact top-4096 (stable-argsort semantics) + bitonic ------
__global__ void __launch_bounds__(1024) k_select() {
    int b = blockIdx.x;
    int tid = threadIdx.x;
    const unsigned* u = g_u + b * NPRED;
    __shared__ unsigned long long keys[TOPK];
    __shared__ int scnt;
    // --- binary search for T = 4096th largest distinct key ((u<<32)|~idx) ---
    unsigned long long T = 0ULL;
    for (int bit = 63; bit >= 0; --bit) {
        unsigned long long cand = T | (1ULL << bit);
        if (tid == 0) scnt = 0;
        __syncthreads();
        int c = 0;
        for (int i = tid; i < NPRED; i += 1024) {
            unsigned long long key = ((unsigned long long)u[i] << 32) | (unsigned)(~i);
            c += (key >= cand);
        }
        #pragma unroll
        for (int o = 16; o; o >>= 1) c += __shfl_down_sync(0xFFFFFFFFu, c, o);
        if ((tid & 31) == 0) atomicAdd(&scnt, c);
        __syncthreads();
        if (scnt >= TOPK) T = cand;
        __syncthreads();
    }
    // --- gather the exactly-4096 keys >= T ---
    if (tid == 0) scnt = 0;
    __syncthreads();
    for (int i = tid; i < NPRED; i += 1024) {
        unsigned long long key = ((unsigned long long)u[i] << 32) | (unsigned)(~i);
        if (key >= T) {
            int p = atomicAdd(&scnt, 1);
            if (p < TOPK) keys[p] = key;
        }
    }
    __syncthreads();
    // --- bitonic sort descending (4096 keys, 1024 threads) ---
    for (int k = 2; k <= TOPK; k <<= 1) {
        for (int j = k >> 1; j > 0; j >>= 1) {
            for (int idx = tid; idx < TOPK; idx += 1024) {
                int l = idx ^ j;
                if (l > idx) {
                    bool desc = (idx & k) == 0;
                    unsigned long long a = keys[idx], c2 = keys[l];
                    if (desc ? (a < c2) : (a > c2)) { keys[idx] = c2; keys[l] = a; }
                }
            }
            __syncthreads();
        }
    }
    // --- emit selection + count valid (s>0) ---
    __shared__ int svalid;
    if (tid == 0) svalid = 0;
    __syncthreads();
    int lv = 0;
    for (int t = tid; t < TOPK; t += 1024) {
        unsigned long long key = keys[t];
        int i = (int)(~(unsigned)(key & 0xFFFFFFFFull));
        float s = g_s[b * NPRED + i];
        g_selIdx[b * TOPK + t] = i;
        g_selScore[b * TOPK + t] = s;
        lv += (s > 0.0f);
    }
    #pragma unroll
    for (int o = 16; o; o >>= 1) lv += __shfl_down_sync(0xFFFFFFFFu, lv, o);
    if ((tid & 31) == 0) atomicAdd(&svalid, lv);
    __syncthreads();
    if (tid == 0) g_nvalid[b] = svalid;
}

// ---------------- kernel 3: gather boxes / class / offset boxes / areas --------------
__global__ void k_gather(const float* __restrict__ pred) {
    int b = blockIdx.y;
    int t = blockIdx.x * 256 + threadIdx.x;
    if (t >= TOPK) return;
    int gi = b * TOPK + t;
    int i = g_selIdx[gi];
    const float* p = pred + ((size_t)b * NPRED + i) * STRIDE;
    float xc = p[0], yc = p[1], w = p[2], h = p[3];
    float hw = __fmul_rn(w, 0.5f), hh = __fmul_rn(h, 0.5f);
    float x1 = __fsub_rn(xc, hw), y1 = __fsub_rn(yc, hh);
    float x2 = __fadd_rn(xc, hw), y2 = __fadd_rn(yc, hh);
    int ci = g_cls[b * NPRED + i];
    float off = __fmul_rn((float)ci, MAX_WH);
    float ox1 = __fadd_rn(x1, off), oy1 = __fadd_rn(y1, off);
    float ox2 = __fadd_rn(x2, off), oy2 = __fadd_rn(y2, off);
    g_box[gi * 4 + 0] = x1; g_box[gi * 4 + 1] = y1;
    g_box[gi * 4 + 2] = x2; g_box[gi * 4 + 3] = y2;
    g_ob[gi * 4 + 0] = ox1; g_ob[gi * 4 + 1] = oy1;
    g_ob[gi * 4 + 2] = ox2; g_ob[gi * 4 + 3] = oy2;
    g_area[gi] = __fmul_rn(__fsub_rn(ox2, ox1), __fsub_rn(oy2, oy1));
    g_selCls[gi] = ci;
}

// ---------------- kernel 4: pairwise suppression mask (upper triangle) ---------------
__global__ void k_mask() {
    int colBlk = blockIdx.x, rowBlk = blockIdx.y, b = blockIdx.z;
    if (colBlk < rowBlk) return;
    int t = threadIdx.x;   // 64 threads
    __shared__ float cbx1[64], cby1[64], cbx2[64], cby2[64], ca[64];
    __shared__ int   cc[64];
    int j = colBlk * 64 + t;
    int gj = b * TOPK + j;
    cbx1[t] = g_ob[gj * 4 + 0]; cby1[t] = g_ob[gj * 4 + 1];
    cbx2[t] = g_ob[gj * 4 + 2]; cby2[t] = g_ob[gj * 4 + 3];
    ca[t] = g_area[gj]; cc[t] = g_selCls[gj];
    __syncthreads();
    int i = rowBlk * 64 + t;
    int gi = b * TOPK + i;
    float rx1 = g_ob[gi * 4 + 0], ry1 = g_ob[gi * 4 + 1];
    float rx2 = g_ob[gi * 4 + 2], ry2 = g_ob[gi * 4 + 3];
    float ra = g_area[gi];
    int rc = g_selCls[gi];
    int colBase = colBlk * 64;
    unsigned long long bits = 0ULL;
    #pragma unroll 4
    for (int c = 0; c < 64; ++c) {
        int jj = colBase + c;
        if (jj <= i) continue;
        if (cc[c] != rc) continue;      // different class => IoU exactly 0 (offset >= 7680)
        float ltx = fmaxf(rx1, cbx1[c]);
        float lty = fmaxf(ry1, cby1[c]);
        float rbx = fminf(rx2, cbx2[c]);
        float rby = fminf(ry2, cby2[c]);
        float wv = fmaxf(__fsub_rn(rbx, ltx), 0.0f);
        float hv = fmaxf(__fsub_rn(rby, lty), 0.0f);
        float inter = __fmul_rn(wv, hv);
        if (inter > 0.0f) {
            float denom = __fadd_rn(__fsub_rn(__fadd_rn(ra, ca[c]), inter), 1e-7f);
            if (__fdiv_rn(inter, denom) > IOU_THRES) bits |= (1ULL << c);
        }
    }
    g_mask[((size_t)b * TOPK + i) * NWORDS + colBlk] = bits;
}

// ---------------- kernel 5: sequential greedy suppression (blocked) ------------------
__global__ void __launch_bounds__(256) k_suppress() {
    int b = blockIdx.x;
    int tid = threadIdx.x;   // 256
    __shared__ unsigned long long removed[NWORDS];
    __shared__ unsigned long long diag[64];
    __shared__ unsigned long long sAlive;
    int nv = g_nvalid[b];
    if (tid < NWORDS) removed[tid] = 0ULL;
    size_t mb = (size_t)b * TOPK * NWORDS;
    __syncthreads();
    for (int blk = 0; blk < NWORDS; ++blk) {
        int base = blk * 64;
        if (tid < 64) diag[tid] = g_mask[mb + (size_t)(base + tid) * NWORDS + blk];
        __syncthreads();
        if (tid == 0) {
            unsigned long long w = removed[blk], alive = 0ULL;
            int lim = nv - base; if (lim > 64) lim = 64;
            #pragma unroll 8
            for (int bb = 0; bb < 64; ++bb) {
                if (bb < lim && !((w >> bb) & 1ULL)) {
                    alive |= (1ULL << bb);
                    w |= diag[bb];
                }
            }
            removed[blk] = w;
            sAlive = alive;
            g_keep[b * NWORDS + blk] = alive;
        }
        __syncthreads();
        unsigned long long alive = sAlive;
        int lane = tid & 63, grp = tid >> 6;
        int w = blk + 1 + lane;
        if (w < NWORDS && alive) {
            unsigned long long acc = 0ULL;
            #pragma unroll 4
            for (int bb = grp; bb < 64; bb += 4) {
                unsigned long long v = g_mask[mb + (size_t)(base + bb) * NWORDS + w];
                if ((alive >> bb) & 1ULL) acc |= v;
            }
            if (acc) atomicOr(&removed[w], acc);
        }
        __syncthreads();
    }
}

// ---------------- kernel 6: compact kept detections into output ----------------------
__global__ void k_output(float* __restrict__ out) {
    int b = blockIdx.x;
    int tid = threadIdx.x;   // 256
    __shared__ unsigned long long km[NWORDS];
    __shared__ int prefix[NWORDS + 1];
    if (tid < NWORDS) km[tid] = g_keep[b * NWORDS + tid];
    __syncthreads();
    if (tid == 0) {
        int s = 0;
        for (int w = 0; w < NWORDS; ++w) { prefix[w] = s; s += __popcll(km[w]); }
        prefix[NWORDS] = s;
    }
    float* o = out + (size_t)b * MAXDET * 6;
    for (int z = tid; z < MAXDET * 6; z += 256) o[z] = 0.0f;
    __syncthreads();
    for (int i = tid; i < TOPK; i += 256) {
        int w = i >> 6, bt = i & 63;
        if ((km[w] >> bt) & 1ULL) {
            int rank = prefix[w] + __popcll(km[w] & ((1ULL << bt) - 1ULL));
            if (rank < MAXDET) {
                int gi = b * TOPK + i;
                float* r = o + rank * 6;
                r[0] = g_box[gi * 4 + 0];
                r[1] = g_box[gi * 4 + 1];
                r[2] = g_box[gi * 4 + 2];
                r[3] = g_box[gi * 4 + 3];
                r[4] = g_selScore[gi];
                r[5] = (float)g_selCls[gi];
            }
        }
    }
}

// ---------------- launch ---------------------------------------------------------------
extern "C" void kernel_launch(void* const* d_in, const int* in_sizes, int n_in,
                              void* d_out, int out_size) {
    const float* pred = (const float*)d_in[0];
    float* out = (float*)d_out;

    // 1) conf / argmax / order key : one warp per row
    {
        int rows = BATCH * NPRED;
        int threads = 256;
        int blocks = (rows * 32 + threads - 1) / threads;
        k_prep<<<blocks, threads>>>(pred);
    }
    // 2) exact top-4096 per batch + sort
    k_select<<<BATCH, 1024>>>();
    // 3) gather selected
    {
        dim3 g((TOPK + 255) / 256, BATCH);
        k_gather<<<g, 256>>>(pred);
    }
    // 4) pairwise IoU mask
    {
        dim3 g(NWORDS, NWORDS, BATCH);
        k_mask<<<g, 64>>>();
    }
    // 5) greedy suppression
    k_suppress<<<BATCH, 256>>>();
    // 6) compact output
    k_output<<<BATCH, 256>>>(out);
}

// round 2
// speedup vs baseline: 1.3004x; 1.3004x over previous
#include <cuda_runtime.h>
#include <cuda_bf16.h>
#include <cstdint>

#define BATCH   16
#define NPRED   25200
#define NC      80
#define STRIDE  85
#define TOPK    4096
#define MAXDET  1000
#define NWORDS  64            // TOPK/64
#define CONF_THRES 0.25f
#define IOU_THRES  0.45f
#define MAX_WH     7680.0f

// ---------------- scratch (no allocation allowed; __device__ globals) ----------------
__device__ unsigned            g_u[BATCH * NPRED];        // order key (score part)
__device__ float               g_s[BATCH * NPRED];        // s = valid ? conf : -1
__device__ int                 g_cls[BATCH * NPRED];      // argmax class
__device__ int                 g_selIdx[BATCH * TOPK];
__device__ float               g_selScore[BATCH * TOPK];
__device__ int                 g_selCls[BATCH * TOPK];
__device__ unsigned            g_clsPack[BATCH * TOPK / 4]; // classes as packed bytes
__device__ float               g_box[BATCH * TOPK * 4];   // xyxy (no offset)
__device__ float               g_ob[BATCH * TOPK * 4];    // offset boxes
__device__ float               g_area[BATCH * TOPK];      // area of offset box
__device__ unsigned long long  g_mask[(size_t)BATCH * TOPK * NWORDS]; // 32MB
__device__ unsigned long long  g_keep[BATCH * NWORDS];
__device__ int                 g_nvalid[BATCH];

// ---------------- kernel 1: conf / argmax / order-key, one warp per row --------------
__global__ void k_prep(const float* __restrict__ pred) {
    int gw   = (blockIdx.x * blockDim.x + threadIdx.x) >> 5;  // global warp = row
    int lane = threadIdx.x & 31;
    if (gw >= BATCH * NPRED) return;
    const float* p = pred + (size_t)gw * STRIDE;
    float obj = p[4];
    float best = -1.0f; int bi = 0;
    #pragma unroll
    for (int c = lane; c < NC; c += 32) {
        float v = __fmul_rn(obj, p[5 + c]);
        if (v > best) { best = v; bi = c; }          // strict > keeps first max
    }
    #pragma unroll
    for (int o = 16; o; o >>= 1) {
        float b2 = __shfl_xor_sync(0xFFFFFFFFu, best, o);
        int   i2 = __shfl_xor_sync(0xFFFFFFFFu, bi, o);
        if (b2 > best || (b2 == best && i2 < bi)) { best = b2; bi = i2; }
    }
    if (lane == 0) {
        float s = (best > CONF_THRES) ? best : -1.0f;
        unsigned ub = __float_as_uint(s);
        unsigned uo = (ub & 0x80000000u) ? ~ub : (ub | 0x80000000u); // ascending order map
        g_s[gw] = s; g_u[gw] = uo; g_cls[gw] = bi;
    }
}

// ---------------- kernel 2: exact top-4096 via 8-pass radix select + bitonic ---------
__global__ void __launch_bounds__(1024) k_select() {
    int b = blockIdx.x;
    int tid = threadIdx.x;
    int lane = tid & 31;
    const unsigned* u = g_u + b * NPRED;
    __shared__ unsigned long long keys[TOPK];
    __shared__ int hist[256];
    __shared__ int scanbuf[256];
    __shared__ unsigned long long sPrefix;
    __shared__ int sNeed;
    __shared__ int scnt;
    if (tid == 0) { sPrefix = 0ULL; sNeed = TOPK; }
    __syncthreads();

    // --- byte-wise radix select for T = TOPK-th largest key ((u<<32)|~idx) ---
    for (int p = 7; p >= 0; --p) {
        int shift = p * 8;
        if (tid < 256) hist[tid] = 0;
        __syncthreads();
        unsigned long long prefix = sPrefix;
        for (int i0 = 0; i0 < NPRED; i0 += 1024) {
            int i = i0 + tid;
            bool inb = i < NPRED;
            unsigned long long key = 0ULL;
            if (inb) key = ((unsigned long long)u[i] << 32) | (unsigned)(~i);
            bool match = inb && (p == 7 || (key >> (shift + 8)) == (prefix >> (shift + 8)));
            unsigned act = __ballot_sync(0xFFFFFFFFu, match);
            if (match) {
                int bin = (int)((key >> shift) & 255ULL);
                unsigned peers = __match_any_sync(act, bin);
                int leader = __ffs(peers) - 1;
                if (lane == leader) atomicAdd(&hist[bin], __popc(peers));
            }
        }
        __syncthreads();
        // reversed inclusive scan: scanbuf[t] = sum of hist[255-t .. 255]
        if (tid < 256) scanbuf[tid] = hist[255 - tid];
        __syncthreads();
        for (int off = 1; off < 256; off <<= 1) {
            int v = 0;
            if (tid < 256 && tid >= off) v = scanbuf[tid - off];
            __syncthreads();
            if (tid < 256) scanbuf[tid] += v;
            __syncthreads();
        }
        if (tid == 0) {
            int need = sNeed;
            int lo = 0, hi = 255;
            while (lo < hi) { int mid = (lo + hi) >> 1; if (scanbuf[mid] >= need) hi = mid; else lo = mid + 1; }
            int above = (lo > 0) ? scanbuf[lo - 1] : 0;
            sNeed = need - above;
            sPrefix = prefix | ((unsigned long long)(255 - lo) << shift);
        }
        __syncthreads();
    }
    unsigned long long T = sPrefix;

    // --- gather the exactly-4096 keys >= T (warp-aggregated positions) ---
    if (tid == 0) scnt = 0;
    __syncthreads();
    for (int i0 = 0; i0 < NPRED; i0 += 1024) {
        int i = i0 + tid;
        bool inb = i < NPRED;
        unsigned long long key = 0ULL;
        if (inb) key = ((unsigned long long)u[i] << 32) | (unsigned)(~i);
        bool m = inb && (key >= T);
        unsigned act = __ballot_sync(0xFFFFFFFFu, m);
        if (m) {
            int leader = __ffs(act) - 1;
            int rank = __popc(act & ((1u << lane) - 1u));
            int base;
            if (lane == leader) base = atomicAdd(&scnt, __popc(act));
            base = __shfl_sync(act, base, leader);
            int pos = base + rank;
            if (pos < TOPK) keys[pos] = key;
        }
    }
    __syncthreads();

    // --- bitonic sort descending (4096 keys, 1024 threads) ---
    for (int k = 2; k <= TOPK; k <<= 1) {
        for (int j = k >> 1; j > 0; j >>= 1) {
            for (int idx = tid; idx < TOPK; idx += 1024) {
                int l = idx ^ j;
                if (l > idx) {
                    bool desc = (idx & k) == 0;
                    unsigned long long a = keys[idx], c2 = keys[l];
                    if (desc ? (a < c2) : (a > c2)) { keys[idx] = c2; keys[l] = a; }
                }
            }
            __syncthreads();
        }
    }

    // --- emit selection + count valid (s>0) ---
    __shared__ int svalid;
    if (tid == 0) svalid = 0;
    __syncthreads();
    int lv = 0;
    for (int t = tid; t < TOPK; t += 1024) {
        unsigned long long key = keys[t];
        int i = (int)(~(unsigned)(key & 0xFFFFFFFFull));
        float s = g_s[b * NPRED + i];
        g_selIdx[b * TOPK + t] = i;
        g_selScore[b * TOPK + t] = s;
        lv += (s > 0.0f);
    }
    #pragma unroll
    for (int o = 16; o; o >>= 1) lv += __shfl_down_sync(0xFFFFFFFFu, lv, o);
    if ((tid & 31) == 0) atomicAdd(&svalid, lv);
    __syncthreads();
    if (tid == 0) g_nvalid[b] = svalid;
}

// ---------------- kernel 3: gather boxes / class / offset boxes / areas --------------
__global__ void k_gather(const float* __restrict__ pred) {
    int b = blockIdx.y;
    int t = blockIdx.x * 256 + threadIdx.x;
    if (t >= TOPK) return;
    int gi = b * TOPK + t;
    int i = g_selIdx[gi];
    const float* p = pred + ((size_t)b * NPRED + i) * STRIDE;
    float xc = p[0], yc = p[1], w = p[2], h = p[3];
    float hw = __fmul_rn(w, 0.5f), hh = __fmul_rn(h, 0.5f);
    float x1 = __fsub_rn(xc, hw), y1 = __fsub_rn(yc, hh);
    float x2 = __fadd_rn(xc, hw), y2 = __fadd_rn(yc, hh);
    int ci = g_cls[b * NPRED + i];
    float off = __fmul_rn((float)ci, MAX_WH);
    float ox1 = __fadd_rn(x1, off), oy1 = __fadd_rn(y1, off);
    float ox2 = __fadd_rn(x2, off), oy2 = __fadd_rn(y2, off);
    g_box[gi * 4 + 0] = x1; g_box[gi * 4 + 1] = y1;
    g_box[gi * 4 + 2] = x2; g_box[gi * 4 + 3] = y2;
    g_ob[gi * 4 + 0] = ox1; g_ob[gi * 4 + 1] = oy1;
    g_ob[gi * 4 + 2] = ox2; g_ob[gi * 4 + 3] = oy2;
    g_area[gi] = __fmul_rn(__fsub_rn(ox2, ox1), __fsub_rn(oy2, oy1));
    g_selCls[gi] = ci;
    ((unsigned char*)g_clsPack)[gi] = (unsigned char)ci;   // packed byte class
}

// ---------------- kernel 4: pairwise suppression mask (upper triangle) ---------------
__global__ void __launch_bounds__(64) k_mask() {
    int colBlk = blockIdx.x, rowBlk = blockIdx.y, b = blockIdx.z;
    if (colBlk < rowBlk) return;
    int t = threadIdx.x;   // 64 threads
    __shared__ float4 cb[64];
    __shared__ float  ca[64];
    __shared__ unsigned ccp[16];
    int colBase = colBlk * 64;
    int gj = b * TOPK + colBase + t;
    cb[t] = ((const float4*)g_ob)[gj];
    ca[t] = g_area[gj];
    if (t < 16) ccp[t] = g_clsPack[b * (TOPK / 4) + colBlk * 16 + t];
    __syncthreads();
    int i = rowBlk * 64 + t;
    int gi = b * TOPK + i;
    float4 rb = ((const float4*)g_ob)[gi];
    float ra = g_area[gi];
    unsigned rc = ((const unsigned char*)g_clsPack)[gi];
    unsigned rc4 = rc * 0x01010101u;
    // branchless same-class candidate mask via packed byte compares
    unsigned lo = 0, hi = 0;
    #pragma unroll
    for (int w = 0; w < 8; ++w) {
        unsigned m = __vcmpeq4(ccp[w], rc4) & 0x01010101u;
        lo |= ((m * 0x01020408u) >> 24) << (4 * w);
    }
    #pragma unroll
    for (int w = 8; w < 16; ++w) {
        unsigned m = __vcmpeq4(ccp[w], rc4) & 0x01010101u;
        hi |= ((m * 0x01020408u) >> 24) << (4 * (w - 8));
    }
    unsigned long long cand = ((unsigned long long)hi << 32) | (unsigned long long)lo;
    if (colBlk == rowBlk) cand = (t == 63) ? 0ULL : (cand & (~0ULL << (t + 1)));
    unsigned long long bits = 0ULL;
    while (cand) {
        int c = __ffsll((long long)cand) - 1;
        cand &= cand - 1;
        float4 cc = cb[c];
        float ltx = fmaxf(rb.x, cc.x);
        float lty = fmaxf(rb.y, cc.y);
        float rbx = fminf(rb.z, cc.z);
        float rby = fminf(rb.w, cc.w);
        float wv = fmaxf(__fsub_rn(rbx, ltx), 0.0f);
        float hv = fmaxf(__fsub_rn(rby, lty), 0.0f);
        float inter = __fmul_rn(wv, hv);
        if (inter > 0.0f) {
            float denom = __fadd_rn(__fsub_rn(__fadd_rn(ra, ca[c]), inter), 1e-7f);
            if (__fdiv_rn(inter, denom) > IOU_THRES) bits |= (1ULL << c);
        }
    }
    g_mask[((size_t)b * TOPK + i) * NWORDS + colBlk] = bits;
}

// ---------------- kernel 5: sequential greedy suppression (blocked) ------------------
__global__ void __launch_bounds__(1024) k_suppress() {
    int b = blockIdx.x;
    int tid = threadIdx.x;   // 1024
    __shared__ unsigned long long removed[NWORDS];
    __shared__ unsigned long long diag[64];
    __shared__ unsigned long long sAlive;
    int nv = g_nvalid[b];
    if (tid < NWORDS) removed[tid] = 0ULL;
    size_t mb = (size_t)b * TOPK * NWORDS;
    __syncthreads();
    for (int blk = 0; blk < NWORDS; ++blk) {
        int base = blk * 64;
        if (tid < 64) diag[tid] = g_mask[mb + (size_t)(base + tid) * NWORDS + blk];
        __syncthreads();
        if (tid == 0) {
            unsigned long long w = removed[blk], alive = 0ULL;
            int lim = nv - base; if (lim > 64) lim = 64;
            #pragma unroll 8
            for (int bb = 0; bb < 64; ++bb) {
                if (bb < lim && !((w >> bb) & 1ULL)) {
                    alive |= (1ULL << bb);
                    w |= diag[bb];
                }
            }
            removed[blk] = w;
            sAlive = alive;
            g_keep[b * NWORDS + blk] = alive;
        }
        __syncthreads();
        unsigned long long alive = sAlive;
        if (alive) {
            int lane = tid & 63, grp = tid >> 6;     // 16 groups of 64 words
            int w = blk + 1 + lane;
            if (w < NWORDS) {
                unsigned long long acc = 0ULL;
                #pragma unroll 4
                for (int bb = grp; bb < 64; bb += 16) {
                    if ((alive >> bb) & 1ULL)
                        acc |= g_mask[mb + (size_t)(base + bb) * NWORDS + w];
                }
                if (acc) atomicOr(&removed[w], acc);
            }
        }
        __syncthreads();
    }
}

// ---------------- kernel 6: compact kept detections into output ----------------------
__global__ void k_output(float* __restrict__ out) {
    int b = blockIdx.x;
    int tid = threadIdx.x;   // 256
    __shared__ unsigned long long km[NWORDS];
    __shared__ int prefix[NWORDS + 1];
    if (tid < NWORDS) km[tid] = g_keep[b * NWORDS + tid];
    __syncthreads();
    if (tid == 0) {
        int s = 0;
        for (int w = 0; w < NWORDS; ++w) { prefix[w] = s; s += __popcll(km[w]); }
        prefix[NWORDS] = s;
    }
    float* o = out + (size_t)b * MAXDET * 6;
    for (int z = tid; z < MAXDET * 6; z += 256) o[z] = 0.0f;
    __syncthreads();
    for (int i = tid; i < TOPK; i += 256) {
        int w = i >> 6, bt = i & 63;
        if ((km[w] >> bt) & 1ULL) {
            int rank = prefix[w] + __popcll(km[w] & ((1ULL << bt) - 1ULL));
            if (rank < MAXDET) {
                int gi = b * TOPK + i;
                float* r = o + rank * 6;
                r[0] = g_box[gi * 4 + 0];
                r[1] = g_box[gi * 4 + 1];
                r[2] = g_box[gi * 4 + 2];
                r[3] = g_box[gi * 4 + 3];
                r[4] = g_selScore[gi];
                r[5] = (float)g_selCls[gi];
            }
        }
    }
}

// ---------------- launch ---------------------------------------------------------------
extern "C" void kernel_launch(void* const* d_in, const int* in_sizes, int n_in,
                              void* d_out, int out_size) {
    const float* pred = (const float*)d_in[0];
    float* out = (float*)d_out;

    // 1) conf / argmax / order key : one warp per row
    {
        int rows = BATCH * NPRED;
        int threads = 256;
        int blocks = (rows * 32 + threads - 1) / threads;
        k_prep<<<blocks, threads>>>(pred);
    }
    // 2) exact top-4096 per batch (radix select) + bitonic sort
    k_select<<<BATCH, 1024>>>();
    // 3) gather selected
    {
        dim3 g((TOPK + 255) / 256, BATCH);
        k_gather<<<g, 256>>>(pred);
    }
    // 4) pairwise IoU mask
    {
        dim3 g(NWORDS, NWORDS, BATCH);
        k_mask<<<g, 64>>>();
    }
    // 5) greedy suppression
    k_suppress<<<BATCH, 1024>>>();
    // 6) compact output
    k_output<<<BATCH, 256>>>(out);
}